// round 1
// baseline (speedup 1.0000x reference)
#include <cuda_runtime.h>
#include <cuda_bf16.h>
#include <math.h>

#define NN 2048
#define EE 32768
#define DD 256
#define HH 8
#define HDm 32
#define DFF 1024

// ---------------- scratch (device globals; no allocation allowed) ----------------
__device__ float    g_Q[NN * DD];
__device__ float    g_K[NN * DD];
__device__ float    g_V[NN * DD];
__device__ float    g_att[NN * DD];
__device__ float    g_proj[NN * DD];
__device__ float    g_h1[NN * DD];
__device__ float    g_f1[NN * DFF];
__device__ float    g_f2[NN * DD];
__device__ float    g_ebias[EE * HH];
__device__ unsigned g_adj[NN * NN / 32];     // adjacency bitmap
__device__ int      g_bidx[NN * NN];         // winning edge index per (src,dst), -1 = none

// ---------------- init: bidx = -1, adj = 0 ----------------
__global__ void clear_kernel() {
    int tid = blockIdx.x * blockDim.x + threadIdx.x;
    if (tid < NN * NN) g_bidx[tid] = -1;
    if (tid < NN * NN / 32) g_adj[tid] = 0u;
}

// ---------------- edge bias: edge_feat[E,10] @ We[10,H] + be ----------------
__global__ void edge_bias_kernel(const float* __restrict__ ef,
                                 const float* __restrict__ We,
                                 const float* __restrict__ be) {
    int tid = blockIdx.x * blockDim.x + threadIdx.x;
    if (tid >= EE * HH) return;
    int e = tid >> 3, h = tid & 7;
    float s = be[h];
    const float* row = ef + e * 10;
#pragma unroll
    for (int k = 0; k < 10; k++) s += row[k] * We[k * HH + h];
    g_ebias[tid] = s;
}

// ---------------- scatter: adjacency bits + last-write bias index ----------------
__global__ void scatter_kernel(const int* __restrict__ src, const int* __restrict__ dst) {
    int tid = blockIdx.x * blockDim.x + threadIdx.x;
    if (tid < EE) {
        int s = src[tid], d = dst[tid];
        int p1 = s * NN + d;
        int p2 = d * NN + s;
        atomicOr(&g_adj[p1 >> 5], 1u << (p1 & 31));
        atomicOr(&g_adj[p2 >> 5], 1u << (p2 & 31));
        atomicMax(&g_bidx[p1], tid);   // last write wins (max edge index)
    } else if (tid < EE + NN) {
        int i = tid - EE;
        int p = i * NN + i;
        atomicOr(&g_adj[p >> 5], 1u << (p & 31));
    }
}

// ---------------- fp32 tiled GEMM: C[M,N] = A[M,K] @ B[K,N] + bias, opt ReLU ----
// BM=BN=64, BK=16, 256 threads, 4x4 per thread.
__global__ void gemm_kernel(const float* __restrict__ A, const float* __restrict__ B,
                            const float* __restrict__ bias, float* __restrict__ C,
                            int M, int K, int N, int doRelu) {
    __shared__ float As[16][65];
    __shared__ float Bs[16][64];
    int tid = threadIdx.x;
    int m0 = blockIdx.y * 64, n0 = blockIdx.x * 64;
    int tx = tid & 15, ty = tid >> 4;
    int ar = tid >> 2, ac = (tid & 3) * 4;
    int br = tid >> 4, bc = (tid & 15) * 4;
    float acc[4][4] = {};
    for (int k0 = 0; k0 < K; k0 += 16) {
        float4 a4 = *(const float4*)(A + (size_t)(m0 + ar) * K + k0 + ac);
        As[ac + 0][ar] = a4.x; As[ac + 1][ar] = a4.y;
        As[ac + 2][ar] = a4.z; As[ac + 3][ar] = a4.w;
        float4 b4 = *(const float4*)(B + (size_t)(k0 + br) * N + n0 + bc);
        *(float4*)&Bs[br][bc] = b4;
        __syncthreads();
#pragma unroll
        for (int k = 0; k < 16; k++) {
            float a[4], b[4];
#pragma unroll
            for (int i = 0; i < 4; i++) a[i] = As[k][ty + 16 * i];
#pragma unroll
            for (int j = 0; j < 4; j++) b[j] = Bs[k][tx + 16 * j];
#pragma unroll
            for (int i = 0; i < 4; i++)
#pragma unroll
                for (int j = 0; j < 4; j++) acc[i][j] = fmaf(a[i], b[j], acc[i][j]);
        }
        __syncthreads();
    }
#pragma unroll
    for (int i = 0; i < 4; i++) {
        int r = m0 + ty + 16 * i;
#pragma unroll
        for (int j = 0; j < 4; j++) {
            int c = n0 + tx + 16 * j;
            float v = acc[i][j] + bias[c];
            if (doRelu) v = fmaxf(v, 0.f);
            C[(size_t)r * N + c] = v;
        }
    }
}

// ---------------- sparse attention: 1 block per node, 1 warp per head ---------
__global__ void attn_kernel() {
    int i = blockIdx.x;
    int lane = threadIdx.x & 31;
    int h = threadIdx.x >> 5;
    __shared__ unsigned adjw[64];
    if (threadIdx.x < 64) adjw[threadIdx.x] = g_adj[i * 64 + threadIdx.x];
    __syncthreads();

    float q = g_Q[i * DD + h * HDm + lane];
    float m = -1e30f, l = 0.f, acc = 0.f;
    const float scale = 0.17677669529663687f;  // 1/sqrt(32)

    for (int wi = 0; wi < 64; wi++) {
        unsigned w = adjw[wi];
        while (w) {
            int b = __ffs(w) - 1;
            w &= w - 1;
            int j = wi * 32 + b;
            float s = q * g_K[j * DD + h * HDm + lane];
#pragma unroll
            for (int o = 16; o > 0; o >>= 1) s += __shfl_xor_sync(0xffffffffu, s, o);
            s *= scale;
            int idx = g_bidx[i * NN + j];
            if (idx >= 0) s += g_ebias[idx * HH + h];
            float nm = fmaxf(m, s);
            float es = __expf(s - nm);
            float sc = __expf(m - nm);
            l = l * sc + es;
            acc = acc * sc + es * g_V[j * DD + h * HDm + lane];
            m = nm;
        }
    }
    g_att[i * DD + h * HDm + lane] = acc / l;
}

// ---------------- fused add + LayerNorm (D=256, block=256) ----------------
__global__ void add_ln_kernel(const float* __restrict__ x, const float* __restrict__ res,
                              const float* __restrict__ w, const float* __restrict__ b,
                              float* __restrict__ out) {
    int i = blockIdx.x, t = threadIdx.x;
    float v = x[i * DD + t] + res[i * DD + t];
    float a = v, a2 = v * v;
#pragma unroll
    for (int o = 16; o > 0; o >>= 1) {
        a += __shfl_xor_sync(0xffffffffu, a, o);
        a2 += __shfl_xor_sync(0xffffffffu, a2, o);
    }
    __shared__ float s1[8], s2[8];
    int warp = t >> 5, lane = t & 31;
    if (lane == 0) { s1[warp] = a; s2[warp] = a2; }
    __syncthreads();
    if (t < 32) {
        float x1 = (t < 8) ? s1[t] : 0.f;
        float x2 = (t < 8) ? s2[t] : 0.f;
#pragma unroll
        for (int o = 4; o > 0; o >>= 1) {
            x1 += __shfl_xor_sync(0xffffffffu, x1, o);
            x2 += __shfl_xor_sync(0xffffffffu, x2, o);
        }
        if (t == 0) { s1[0] = x1; s2[0] = x2; }
    }
    __syncthreads();
    float mu = s1[0] * (1.f / 256.f);
    float var = s2[0] * (1.f / 256.f) - mu * mu;
    out[i * DD + t] = (v - mu) * rsqrtf(var + 1e-5f) * w[t] + b[t];
}

// ---------------- launch ----------------
extern "C" void kernel_launch(void* const* d_in, const int* in_sizes, int n_in,
                              void* d_out, int out_size) {
    const float* node_feat = (const float*)d_in[0];
    const float* edge_feat = (const float*)d_in[1];
    const int*   src       = (const int*)d_in[2];
    const int*   dst       = (const int*)d_in[3];
    const float* Wq = (const float*)d_in[4];  const float* bq = (const float*)d_in[5];
    const float* Wk = (const float*)d_in[6];  const float* bk = (const float*)d_in[7];
    const float* Wv = (const float*)d_in[8];  const float* bv = (const float*)d_in[9];
    const float* Wo = (const float*)d_in[10]; const float* bo = (const float*)d_in[11];
    const float* We = (const float*)d_in[12]; const float* be = (const float*)d_in[13];
    const float* n1w = (const float*)d_in[14]; const float* n1b = (const float*)d_in[15];
    const float* W1 = (const float*)d_in[16]; const float* b1 = (const float*)d_in[17];
    const float* W2 = (const float*)d_in[18]; const float* b2 = (const float*)d_in[19];
    const float* n2w = (const float*)d_in[20]; const float* n2b = (const float*)d_in[21];
    float* out = (float*)d_out;

    // resolve device-global addresses for GEMM args
    float *Qp, *Kp, *Vp, *attp, *projp, *h1p, *f1p, *f2p;
    cudaGetSymbolAddress((void**)&Qp, g_Q);
    cudaGetSymbolAddress((void**)&Kp, g_K);
    cudaGetSymbolAddress((void**)&Vp, g_V);
    cudaGetSymbolAddress((void**)&attp, g_att);
    cudaGetSymbolAddress((void**)&projp, g_proj);
    cudaGetSymbolAddress((void**)&h1p, g_h1);
    cudaGetSymbolAddress((void**)&f1p, g_f1);
    cudaGetSymbolAddress((void**)&f2p, g_f2);

    // 1. clear bias-index map + adjacency bitmap
    clear_kernel<<<(NN * NN + 255) / 256, 256>>>();
    // 2. edge bias
    edge_bias_kernel<<<(EE * HH + 255) / 256, 256>>>(edge_feat, We, be);
    // 3. scatter adjacency + bias index
    scatter_kernel<<<(EE + NN + 255) / 256, 256>>>(src, dst);
    // 4. Q, K, V GEMMs
    dim3 g256(DD / 64, NN / 64);
    gemm_kernel<<<g256, 256>>>(node_feat, Wq, bq, Qp, NN, DD, DD, 0);
    gemm_kernel<<<g256, 256>>>(node_feat, Wk, bk, Kp, NN, DD, DD, 0);
    gemm_kernel<<<g256, 256>>>(node_feat, Wv, bv, Vp, NN, DD, DD, 0);
    // 5. sparse attention
    attn_kernel<<<NN, 256>>>();
    // 6. output projection + add&LN
    gemm_kernel<<<g256, 256>>>(attp, Wo, bo, projp, NN, DD, DD, 0);
    add_ln_kernel<<<NN, 256>>>(projp, node_feat, n1w, n1b, h1p);
    // 7. FFN
    dim3 gff1(DFF / 64, NN / 64);
    gemm_kernel<<<gff1, 256>>>(h1p, W1, b1, f1p, NN, DD, DFF, 1);
    gemm_kernel<<<g256, 256>>>(f1p, W2, b2, f2p, NN, DFF, DD, 0);
    // 8. final add&LN -> output
    add_ln_kernel<<<NN, 256>>>(h1p, f2p, n2w, n2b, out);
}

// round 3
// speedup vs baseline: 1.3297x; 1.3297x over previous
#include <cuda_runtime.h>
#include <cuda_bf16.h>
#include <math.h>
#include <stdint.h>

#define NN 2048
#define EE 32768
#define DD 256
#define HH 8
#define HDm 32
#define DFF 1024

// ---------------- scratch (device globals; no allocation allowed) ----------------
__device__ float    g_Q[NN * DD];
__device__ float    g_K[NN * DD];
__device__ float    g_V[NN * DD];
__device__ float    g_att[NN * DD];
__device__ float    g_proj[NN * DD];
__device__ float    g_h1[NN * DD];
__device__ float    g_f1[NN * DFF];
__device__ float    g_f2[NN * DD];
__device__ float    g_ebias[EE * HH];
__device__ unsigned g_adj[NN * NN / 32];
__device__ int      g_bidx[NN * NN];

// ---------------- warp MMA: m16n8k16 bf16 -> fp32 ----------------
__device__ __forceinline__ void mma_bf16(float* d, const uint32_t* a, const uint32_t* b) {
    asm volatile(
        "mma.sync.aligned.m16n8k16.row.col.f32.bf16.bf16.f32 "
        "{%0,%1,%2,%3}, {%4,%5,%6,%7}, {%8,%9}, {%0,%1,%2,%3};"
        : "+f"(d[0]), "+f"(d[1]), "+f"(d[2]), "+f"(d[3])
        : "r"(a[0]), "r"(a[1]), "r"(a[2]), "r"(a[3]), "r"(b[0]), "r"(b[1]));
}

__device__ __forceinline__ uint32_t pack_hi(float f0, float f1) {
    __nv_bfloat16 h0 = __float2bfloat16(f0), h1 = __float2bfloat16(f1);
    return (uint32_t)__bfloat16_as_ushort(h0) | ((uint32_t)__bfloat16_as_ushort(h1) << 16);
}
__device__ __forceinline__ uint32_t pack_lo(float f0, float f1) {
    __nv_bfloat16 h0 = __float2bfloat16(f0), h1 = __float2bfloat16(f1);
    __nv_bfloat16 l0 = __float2bfloat16(f0 - __bfloat162float(h0));
    __nv_bfloat16 l1 = __float2bfloat16(f1 - __bfloat162float(h1));
    return (uint32_t)__bfloat16_as_ushort(l0) | ((uint32_t)__bfloat16_as_ushort(l1) << 16);
}

// ================= tensor-core GEMM: C[M,N] = A[M,K] @ B[K,N] + bias =================
// Block tile 64x64, BK=32, 128 threads (4 warps, 32x32 warp tiles).
// bf16 hi/lo split: 3 mma terms ~ fp32 precision. grid.z selects weight set (QKV fusion).
#define SPAD 40   // smem row stride in bf16 (conflict-breaking)

__global__ void __launch_bounds__(128) gemm_mma(
    const float* __restrict__ A,
    const float* __restrict__ B0, const float* __restrict__ B1, const float* __restrict__ B2,
    const float* __restrict__ bias0, const float* __restrict__ bias1, const float* __restrict__ bias2,
    float* __restrict__ C0, float* __restrict__ C1, float* __restrict__ C2,
    int K, int N, int doRelu)
{
    const float* B = B0; const float* bias = bias0; float* C = C0;
    if (blockIdx.z == 1) { B = B1; bias = bias1; C = C1; }
    if (blockIdx.z == 2) { B = B2; bias = bias2; C = C2; }

    __shared__ __align__(16) __nv_bfloat16 AsH[64 * SPAD];
    __shared__ __align__(16) __nv_bfloat16 AsL[64 * SPAD];
    __shared__ __align__(16) __nv_bfloat16 BsH[64 * SPAD];   // transposed: [n][k]
    __shared__ __align__(16) __nv_bfloat16 BsL[64 * SPAD];

    const int tid = threadIdx.x;
    const int lane = tid & 31;
    const int wid = tid >> 5;
    const int wm = wid >> 1;          // 0..1 (M)
    const int wn = wid & 1;           // 0..1 (N)
    const int g = lane >> 2;          // group id 0..7
    const int tg = lane & 3;          // thread-in-group

    const int m0 = blockIdx.y * 64;
    const int n0 = blockIdx.x * 64;

    float acc[2][4][4];
#pragma unroll
    for (int i = 0; i < 2; i++)
#pragma unroll
        for (int j = 0; j < 4; j++)
#pragma unroll
            for (int c = 0; c < 4; c++) acc[i][j][c] = 0.f;

    const int nk = K >> 5;
    for (int kc = 0; kc < nk; kc++) {
        // ---- global loads (fp32) ----
        float4 av[4], bv[4];
#pragma unroll
        for (int it = 0; it < 4; it++) {
            int flat = tid * 4 + it * 512;          // A: 64 x 32
            int r = flat >> 5, c = flat & 31;
            av[it] = *(const float4*)(A + (size_t)(m0 + r) * K + kc * 32 + c);
        }
#pragma unroll
        for (int it = 0; it < 4; it++) {
            int flat = tid * 4 + it * 512;          // B: 32(k) x 64(n)
            int k = flat >> 6, n = flat & 63;
            bv[it] = *(const float4*)(B + (size_t)(kc * 32 + k) * N + n0 + n);
        }
        __syncthreads();    // prior iter's fragment reads done before overwrite

        // ---- convert + store A (row-major [m][k], hi/lo) ----
#pragma unroll
        for (int it = 0; it < 4; it++) {
            int flat = tid * 4 + it * 512;
            int r = flat >> 5, c = flat & 31;
            uint2 ph, pl;
            ph.x = pack_hi(av[it].x, av[it].y); ph.y = pack_hi(av[it].z, av[it].w);
            pl.x = pack_lo(av[it].x, av[it].y); pl.y = pack_lo(av[it].z, av[it].w);
            *(uint2*)&AsH[r * SPAD + c] = ph;
            *(uint2*)&AsL[r * SPAD + c] = pl;
        }
        // ---- convert + transpose-store B ([n][k], hi/lo) ----
#pragma unroll
        for (int it = 0; it < 4; it++) {
            int flat = tid * 4 + it * 512;
            int k = flat >> 6, n = flat & 63;
            float fv[4] = {bv[it].x, bv[it].y, bv[it].z, bv[it].w};
#pragma unroll
            for (int j = 0; j < 4; j++) {
                __nv_bfloat16 h = __float2bfloat16(fv[j]);
                __nv_bfloat16 l = __float2bfloat16(fv[j] - __bfloat162float(h));
                BsH[(n + j) * SPAD + k] = h;
                BsL[(n + j) * SPAD + k] = l;
            }
        }
        __syncthreads();

        // ---- compute: 2 k16 chunks x 3 split terms x (2x4 tiles) ----
#pragma unroll
        for (int kk = 0; kk < 2; kk++) {
            const int kb = kk * 16;
            uint32_t ah[2][4], al[2][4], bh[4][2], bl[4][2];
#pragma unroll
            for (int i = 0; i < 2; i++) {
                int rb = (wm * 32 + i * 16 + g) * SPAD + kb + tg * 2;
                ah[i][0] = *(const uint32_t*)&AsH[rb];
                ah[i][1] = *(const uint32_t*)&AsH[rb + 8 * SPAD];
                ah[i][2] = *(const uint32_t*)&AsH[rb + 8];
                ah[i][3] = *(const uint32_t*)&AsH[rb + 8 * SPAD + 8];
                al[i][0] = *(const uint32_t*)&AsL[rb];
                al[i][1] = *(const uint32_t*)&AsL[rb + 8 * SPAD];
                al[i][2] = *(const uint32_t*)&AsL[rb + 8];
                al[i][3] = *(const uint32_t*)&AsL[rb + 8 * SPAD + 8];
            }
#pragma unroll
            for (int j = 0; j < 4; j++) {
                int rb = (wn * 32 + j * 8 + g) * SPAD + kb + tg * 2;
                bh[j][0] = *(const uint32_t*)&BsH[rb];
                bh[j][1] = *(const uint32_t*)&BsH[rb + 8];
                bl[j][0] = *(const uint32_t*)&BsL[rb];
                bl[j][1] = *(const uint32_t*)&BsL[rb + 8];
            }
#pragma unroll
            for (int i = 0; i < 2; i++)
#pragma unroll
                for (int j = 0; j < 4; j++) mma_bf16(acc[i][j], ah[i], bh[j]);
#pragma unroll
            for (int i = 0; i < 2; i++)
#pragma unroll
                for (int j = 0; j < 4; j++) mma_bf16(acc[i][j], ah[i], bl[j]);
#pragma unroll
            for (int i = 0; i < 2; i++)
#pragma unroll
                for (int j = 0; j < 4; j++) mma_bf16(acc[i][j], al[i], bh[j]);
        }
    }

    // ---- epilogue: bias (+ReLU), fp32 stores ----
#pragma unroll
    for (int i = 0; i < 2; i++) {
        int row = m0 + wm * 32 + i * 16 + g;
#pragma unroll
        for (int j = 0; j < 4; j++) {
            int col = n0 + wn * 32 + j * 8 + tg * 2;
            float b0f = bias[col], b1f = bias[col + 1];
            float v0 = acc[i][j][0] + b0f, v1 = acc[i][j][1] + b1f;
            float v2 = acc[i][j][2] + b0f, v3 = acc[i][j][3] + b1f;
            if (doRelu) {
                v0 = fmaxf(v0, 0.f); v1 = fmaxf(v1, 0.f);
                v2 = fmaxf(v2, 0.f); v3 = fmaxf(v3, 0.f);
            }
            *(float2*)(C + (size_t)row * N + col) = make_float2(v0, v1);
            *(float2*)(C + (size_t)(row + 8) * N + col) = make_float2(v2, v3);
        }
    }
}

// ---------------- init: bidx = -1, adj = 0 ----------------
__global__ void clear_kernel() {
    int tid = blockIdx.x * blockDim.x + threadIdx.x;
    if (tid < NN * NN) g_bidx[tid] = -1;
    if (tid < NN * NN / 32) g_adj[tid] = 0u;
}

// ---------------- edge bias: edge_feat[E,10] @ We[10,H] + be ----------------
__global__ void edge_bias_kernel(const float* __restrict__ ef,
                                 const float* __restrict__ We,
                                 const float* __restrict__ be) {
    int tid = blockIdx.x * blockDim.x + threadIdx.x;
    if (tid >= EE * HH) return;
    int e = tid >> 3, h = tid & 7;
    float s = be[h];
    const float* row = ef + e * 10;
#pragma unroll
    for (int k = 0; k < 10; k++) s += row[k] * We[k * HH + h];
    g_ebias[tid] = s;
}

// ---------------- scatter: adjacency bits + last-write bias index ----------------
__global__ void scatter_kernel(const int* __restrict__ src, const int* __restrict__ dst) {
    int tid = blockIdx.x * blockDim.x + threadIdx.x;
    if (tid < EE) {
        int s = src[tid], d = dst[tid];
        int p1 = s * NN + d;
        int p2 = d * NN + s;
        atomicOr(&g_adj[p1 >> 5], 1u << (p1 & 31));
        atomicOr(&g_adj[p2 >> 5], 1u << (p2 & 31));
        atomicMax(&g_bidx[p1], tid);
    } else if (tid < EE + NN) {
        int i = tid - EE;
        int p = i * NN + i;
        atomicOr(&g_adj[p >> 5], 1u << (p & 31));
    }
}

// ---------------- sparse attention: 1 block per node, 1 warp per head ---------
__global__ void attn_kernel() {
    int i = blockIdx.x;
    int lane = threadIdx.x & 31;
    int h = threadIdx.x >> 5;
    __shared__ unsigned adjw[64];
    if (threadIdx.x < 64) adjw[threadIdx.x] = g_adj[i * 64 + threadIdx.x];
    __syncthreads();

    float q = g_Q[i * DD + h * HDm + lane];
    float m = -1e30f, l = 0.f, acc = 0.f;
    const float scale = 0.17677669529663687f;

    for (int wi = 0; wi < 64; wi++) {
        unsigned w = adjw[wi];
        while (w) {
            int b = __ffs(w) - 1;
            w &= w - 1;
            int j = wi * 32 + b;
            float s = q * g_K[j * DD + h * HDm + lane];
#pragma unroll
            for (int o = 16; o > 0; o >>= 1) s += __shfl_xor_sync(0xffffffffu, s, o);
            s *= scale;
            int idx = g_bidx[i * NN + j];
            if (idx >= 0) s += g_ebias[idx * HH + h];
            float nm = fmaxf(m, s);
            float es = __expf(s - nm);
            float sc = __expf(m - nm);
            l = l * sc + es;
            acc = acc * sc + es * g_V[j * DD + h * HDm + lane];
            m = nm;
        }
    }
    g_att[i * DD + h * HDm + lane] = acc / l;
}

// ---------------- fused add + LayerNorm (D=256, block=256) ----------------
__global__ void add_ln_kernel(const float* __restrict__ x, const float* __restrict__ res,
                              const float* __restrict__ w, const float* __restrict__ b,
                              float* __restrict__ out) {
    int i = blockIdx.x, t = threadIdx.x;
    float v = x[i * DD + t] + res[i * DD + t];
    float a = v, a2 = v * v;
#pragma unroll
    for (int o = 16; o > 0; o >>= 1) {
        a += __shfl_xor_sync(0xffffffffu, a, o);
        a2 += __shfl_xor_sync(0xffffffffu, a2, o);
    }
    __shared__ float s1[8], s2[8];
    int warp = t >> 5, lane = t & 31;
    if (lane == 0) { s1[warp] = a; s2[warp] = a2; }
    __syncthreads();
    if (t < 32) {
        float x1 = (t < 8) ? s1[t] : 0.f;
        float x2 = (t < 8) ? s2[t] : 0.f;
#pragma unroll
        for (int o = 4; o > 0; o >>= 1) {
            x1 += __shfl_xor_sync(0xffffffffu, x1, o);
            x2 += __shfl_xor_sync(0xffffffffu, x2, o);
        }
        if (t == 0) { s1[0] = x1; s2[0] = x2; }
    }
    __syncthreads();
    float mu = s1[0] * (1.f / 256.f);
    float var = s2[0] * (1.f / 256.f) - mu * mu;
    out[i * DD + t] = (v - mu) * rsqrtf(var + 1e-5f) * w[t] + b[t];
}

// ---------------- launch ----------------
extern "C" void kernel_launch(void* const* d_in, const int* in_sizes, int n_in,
                              void* d_out, int out_size) {
    const float* node_feat = (const float*)d_in[0];
    const float* edge_feat = (const float*)d_in[1];
    const int*   src       = (const int*)d_in[2];
    const int*   dst       = (const int*)d_in[3];
    const float* Wq = (const float*)d_in[4];  const float* bq = (const float*)d_in[5];
    const float* Wk = (const float*)d_in[6];  const float* bk = (const float*)d_in[7];
    const float* Wv = (const float*)d_in[8];  const float* bv = (const float*)d_in[9];
    const float* Wo = (const float*)d_in[10]; const float* bo = (const float*)d_in[11];
    const float* We = (const float*)d_in[12]; const float* be = (const float*)d_in[13];
    const float* n1w = (const float*)d_in[14]; const float* n1b = (const float*)d_in[15];
    const float* W1 = (const float*)d_in[16]; const float* b1 = (const float*)d_in[17];
    const float* W2 = (const float*)d_in[18]; const float* b2 = (const float*)d_in[19];
    const float* n2w = (const float*)d_in[20]; const float* n2b = (const float*)d_in[21];
    float* out = (float*)d_out;

    float *Qp, *Kp, *Vp, *attp, *projp, *h1p, *f1p, *f2p;
    cudaGetSymbolAddress((void**)&Qp, g_Q);
    cudaGetSymbolAddress((void**)&Kp, g_K);
    cudaGetSymbolAddress((void**)&Vp, g_V);
    cudaGetSymbolAddress((void**)&attp, g_att);
    cudaGetSymbolAddress((void**)&projp, g_proj);
    cudaGetSymbolAddress((void**)&h1p, g_h1);
    cudaGetSymbolAddress((void**)&f1p, g_f1);
    cudaGetSymbolAddress((void**)&f2p, g_f2);

    clear_kernel<<<(NN * NN + 255) / 256, 256>>>();
    edge_bias_kernel<<<(EE * HH + 255) / 256, 256>>>(edge_feat, We, be);
    scatter_kernel<<<(EE + NN + 255) / 256, 256>>>(src, dst);

    // QKV fused via grid.z
    gemm_mma<<<dim3(DD / 64, NN / 64, 3), 128>>>(
        node_feat, Wq, Wk, Wv, bq, bk, bv, Qp, Kp, Vp, DD, DD, 0);

    attn_kernel<<<NN, 256>>>();

    gemm_mma<<<dim3(DD / 64, NN / 64, 1), 128>>>(
        attp, Wo, Wo, Wo, bo, bo, bo, projp, projp, projp, DD, DD, 0);
    add_ln_kernel<<<NN, 256>>>(projp, node_feat, n1w, n1b, h1p);

    gemm_mma<<<dim3(DFF / 64, NN / 64, 1), 128>>>(
        h1p, W1, W1, W1, b1, b1, b1, f1p, f1p, f1p, DD, DFF, 1);
    gemm_mma<<<dim3(DD / 64, NN / 64, 1), 128>>>(
        f1p, W2, W2, W2, b2, b2, b2, f2p, f2p, f2p, DFF, DD, 0);

    add_ln_kernel<<<NN, 256>>>(h1p, f2p, n2w, n2b, out);
}

// round 4
// speedup vs baseline: 1.8397x; 1.3835x over previous
#include <cuda_runtime.h>
#include <cuda_bf16.h>
#include <math.h>
#include <stdint.h>

#define NN 2048
#define EE 32768
#define DD 256
#define HH 8
#define HDm 32
#define DFF 1024

// ---------------- scratch (device globals) ----------------
__device__ float    g_Q[NN * DD];
__device__ float    g_K[NN * DD];
__device__ float    g_V[NN * DD];
__device__ float    g_proj[NN * DD];
__device__ float    g_h1[NN * DD];
__device__ float    g_f2[NN * DD];
__device__ float    g_ebias[EE * HH];
__device__ unsigned g_adj[NN * NN / 32];
__device__ int      g_bidx[NN * NN];

// bf16 hi/lo pairs (pre-split fp32)
__device__ __nv_bfloat16 g_nfH[NN * DD],  g_nfL[NN * DD];
__device__ __nv_bfloat16 g_WqH[DD * DD],  g_WqL[DD * DD];
__device__ __nv_bfloat16 g_WkH[DD * DD],  g_WkL[DD * DD];
__device__ __nv_bfloat16 g_WvH[DD * DD],  g_WvL[DD * DD];
__device__ __nv_bfloat16 g_WoH[DD * DD],  g_WoL[DD * DD];
__device__ __nv_bfloat16 g_W1H[DD * DFF], g_W1L[DD * DFF];
__device__ __nv_bfloat16 g_W2H[DFF * DD], g_W2L[DFF * DD];
__device__ __nv_bfloat16 g_attH[NN * DD], g_attL[NN * DD];
__device__ __nv_bfloat16 g_h1H[NN * DD],  g_h1L[NN * DD];
__device__ __nv_bfloat16 g_f1H[NN * DFF], g_f1L[NN * DFF];

// ---------------- helpers ----------------
__device__ __forceinline__ uint32_t smem_u32(const void* p) {
    uint32_t a;
    asm("{ .reg .u64 t; cvta.to.shared.u64 t, %1; cvt.u32.u64 %0, t; }" : "=r"(a) : "l"(p));
    return a;
}
__device__ __forceinline__ void mma_bf16(float* d, const uint32_t* a, const uint32_t* b) {
    asm volatile(
        "mma.sync.aligned.m16n8k16.row.col.f32.bf16.bf16.f32 "
        "{%0,%1,%2,%3}, {%4,%5,%6,%7}, {%8,%9}, {%0,%1,%2,%3};"
        : "+f"(d[0]), "+f"(d[1]), "+f"(d[2]), "+f"(d[3])
        : "r"(a[0]), "r"(a[1]), "r"(a[2]), "r"(a[3]), "r"(b[0]), "r"(b[1]));
}
#define LDSM4(d0, d1, d2, d3, a) \
    asm volatile("ldmatrix.sync.aligned.m8n8.x4.shared.b16 {%0,%1,%2,%3},[%4];" \
        : "=r"(d0), "=r"(d1), "=r"(d2), "=r"(d3) : "r"(a))
#define LDSM4T(d0, d1, d2, d3, a) \
    asm volatile("ldmatrix.sync.aligned.m8n8.x4.trans.shared.b16 {%0,%1,%2,%3},[%4];" \
        : "=r"(d0), "=r"(d1), "=r"(d2), "=r"(d3) : "r"(a))

__device__ __forceinline__ uint32_t pack_hi(float f0, float f1) {
    __nv_bfloat16 h0 = __float2bfloat16(f0), h1 = __float2bfloat16(f1);
    return (uint32_t)__bfloat16_as_ushort(h0) | ((uint32_t)__bfloat16_as_ushort(h1) << 16);
}
__device__ __forceinline__ uint32_t pack_lo(float f0, float f1) {
    __nv_bfloat16 h0 = __float2bfloat16(f0), h1 = __float2bfloat16(f1);
    __nv_bfloat16 l0 = __float2bfloat16(f0 - __bfloat162float(h0));
    __nv_bfloat16 l1 = __float2bfloat16(f1 - __bfloat162float(h1));
    return (uint32_t)__bfloat16_as_ushort(l0) | ((uint32_t)__bfloat16_as_ushort(l1) << 16);
}

// ================= GEMM: C[M,N] = A @ B, A/B pre-split bf16 hi/lo =================
// 64x64 tile, BK=32, 128 threads (4 warps, 32x32 warp tiles), ldmatrix fragments.
// flags: 1=RELU, 2=ATOMIC (split-K, no bias), 4=OUT_PAIR(bf16 hi/lo out), 8=z is weight-select
#define ASTR 40
#define BSTR 72

__global__ void __launch_bounds__(128) gemm_tc(
    const __nv_bfloat16* __restrict__ AH, const __nv_bfloat16* __restrict__ AL,
    const __nv_bfloat16* __restrict__ BH0, const __nv_bfloat16* __restrict__ BH1, const __nv_bfloat16* __restrict__ BH2,
    const __nv_bfloat16* __restrict__ BL0, const __nv_bfloat16* __restrict__ BL1, const __nv_bfloat16* __restrict__ BL2,
    const float* __restrict__ bias0, const float* __restrict__ bias1, const float* __restrict__ bias2,
    float* __restrict__ C0, float* __restrict__ C1, float* __restrict__ C2,
    __nv_bfloat16* __restrict__ CH, __nv_bfloat16* __restrict__ CL,
    int K, int N, int flags)
{
    __shared__ __align__(16) __nv_bfloat16 AsH[64 * ASTR];
    __shared__ __align__(16) __nv_bfloat16 AsL[64 * ASTR];
    __shared__ __align__(16) __nv_bfloat16 BsH[32 * BSTR];
    __shared__ __align__(16) __nv_bfloat16 BsL[32 * BSTR];

    const __nv_bfloat16* BH = BH0; const __nv_bfloat16* BL = BL0;
    const float* bias = bias0; float* C = C0;
    int kslice = 0, nsl = 1;
    if (flags & 8) {
        if (blockIdx.z == 1) { BH = BH1; BL = BL1; bias = bias1; C = C1; }
        else if (blockIdx.z == 2) { BH = BH2; BL = BL2; bias = bias2; C = C2; }
    } else { kslice = blockIdx.z; nsl = gridDim.z; }

    const int tid = threadIdx.x;
    const int lane = tid & 31;
    const int wid = tid >> 5;
    const int wm = wid >> 1, wn = wid & 1;
    const int g = lane >> 2, tg = lane & 3;
    const int m0 = blockIdx.y * 64;
    const int n0 = blockIdx.x * 64;

    const int nkTot = K >> 5;
    const int nk = nkTot / nsl;
    const int kstart = kslice * nk;

    float acc[2][4][4];
#pragma unroll
    for (int i = 0; i < 2; i++)
#pragma unroll
        for (int j = 0; j < 4; j++)
#pragma unroll
            for (int c = 0; c < 4; c++) acc[i][j][c] = 0.f;

    // lane-dependent ldmatrix base addresses
    const uint32_t aBaseH = smem_u32(AsH) + (((wm * 32 + (lane & 15)) * ASTR + ((lane >> 4) << 3)) << 1);
    const uint32_t aBaseL = smem_u32(AsL) + (((wm * 32 + (lane & 15)) * ASTR + ((lane >> 4) << 3)) << 1);
    const uint32_t bBaseH = smem_u32(BsH) + ((((lane & 15)) * BSTR + wn * 32 + ((lane >> 4) << 3)) << 1);
    const uint32_t bBaseL = smem_u32(BsL) + ((((lane & 15)) * BSTR + wn * 32 + ((lane >> 4) << 3)) << 1);

    uint2 rAH[4], rAL[4], rBH[4], rBL[4];

#define LOADC(KC) do { \
    _Pragma("unroll") \
    for (int it = 0; it < 4; it++) { \
        int flat = tid * 4 + it * 512; \
        int r = flat >> 5, c = flat & 31; \
        size_t gi = (size_t)(m0 + r) * K + (KC) * 32 + c; \
        rAH[it] = *(const uint2*)(AH + gi); \
        rAL[it] = *(const uint2*)(AL + gi); \
        int k = flat >> 6, n = flat & 63; \
        size_t gj = (size_t)((KC) * 32 + k) * N + n0 + n; \
        rBH[it] = *(const uint2*)(BH + gj); \
        rBL[it] = *(const uint2*)(BL + gj); \
    } } while (0)

    LOADC(kstart);

    for (int kc = 0; kc < nk; kc++) {
        // store staged regs -> smem
#pragma unroll
        for (int it = 0; it < 4; it++) {
            int flat = tid * 4 + it * 512;
            int r = flat >> 5, c = flat & 31;
            *(uint2*)&AsH[r * ASTR + c] = rAH[it];
            *(uint2*)&AsL[r * ASTR + c] = rAL[it];
            int k = flat >> 6, n = flat & 63;
            *(uint2*)&BsH[k * BSTR + n] = rBH[it];
            *(uint2*)&BsL[k * BSTR + n] = rBL[it];
        }
        __syncthreads();
        if (kc + 1 < nk) LOADC(kstart + kc + 1);   // overlap next loads with MMA

#pragma unroll
        for (int kk = 0; kk < 2; kk++) {
            const int kb = kk * 16;
            uint32_t ah[2][4], al[2][4], bh[4][2], bl[4][2];
            LDSM4(ah[0][0], ah[0][1], ah[0][2], ah[0][3], aBaseH + (kb << 1));
            LDSM4(ah[1][0], ah[1][1], ah[1][2], ah[1][3], aBaseH + ((16 * ASTR + kb) << 1));
            LDSM4(al[0][0], al[0][1], al[0][2], al[0][3], aBaseL + (kb << 1));
            LDSM4(al[1][0], al[1][1], al[1][2], al[1][3], aBaseL + ((16 * ASTR + kb) << 1));
            LDSM4T(bh[0][0], bh[0][1], bh[1][0], bh[1][1], bBaseH + ((kb * BSTR) << 1));
            LDSM4T(bh[2][0], bh[2][1], bh[3][0], bh[3][1], bBaseH + ((kb * BSTR + 16) << 1));
            LDSM4T(bl[0][0], bl[0][1], bl[1][0], bl[1][1], bBaseL + ((kb * BSTR) << 1));
            LDSM4T(bl[2][0], bl[2][1], bl[3][0], bl[3][1], bBaseL + ((kb * BSTR + 16) << 1));
#pragma unroll
            for (int i = 0; i < 2; i++)
#pragma unroll
                for (int j = 0; j < 4; j++) mma_bf16(acc[i][j], ah[i], bh[j]);
#pragma unroll
            for (int i = 0; i < 2; i++)
#pragma unroll
                for (int j = 0; j < 4; j++) mma_bf16(acc[i][j], ah[i], bl[j]);
#pragma unroll
            for (int i = 0; i < 2; i++)
#pragma unroll
                for (int j = 0; j < 4; j++) mma_bf16(acc[i][j], al[i], bh[j]);
        }
        __syncthreads();
    }

    // ---- epilogue ----
#pragma unroll
    for (int i = 0; i < 2; i++) {
        int row = m0 + wm * 32 + i * 16 + g;
#pragma unroll
        for (int j = 0; j < 4; j++) {
            int col = n0 + wn * 32 + j * 8 + tg * 2;
            float v0 = acc[i][j][0], v1 = acc[i][j][1], v2 = acc[i][j][2], v3 = acc[i][j][3];
            if (flags & 2) {
                atomicAdd(C + (size_t)row * N + col, v0);
                atomicAdd(C + (size_t)row * N + col + 1, v1);
                atomicAdd(C + (size_t)(row + 8) * N + col, v2);
                atomicAdd(C + (size_t)(row + 8) * N + col + 1, v3);
            } else {
                float b0f = bias[col], b1f = bias[col + 1];
                v0 += b0f; v1 += b1f; v2 += b0f; v3 += b1f;
                if (flags & 1) {
                    v0 = fmaxf(v0, 0.f); v1 = fmaxf(v1, 0.f);
                    v2 = fmaxf(v2, 0.f); v3 = fmaxf(v3, 0.f);
                }
                if (flags & 4) {
                    *(uint32_t*)&CH[(size_t)row * N + col] = pack_hi(v0, v1);
                    *(uint32_t*)&CL[(size_t)row * N + col] = pack_lo(v0, v1);
                    *(uint32_t*)&CH[(size_t)(row + 8) * N + col] = pack_hi(v2, v3);
                    *(uint32_t*)&CL[(size_t)(row + 8) * N + col] = pack_lo(v2, v3);
                } else {
                    *(float2*)(C + (size_t)row * N + col) = make_float2(v0, v1);
                    *(float2*)(C + (size_t)(row + 8) * N + col) = make_float2(v2, v3);
                }
            }
        }
    }
}

// ---------------- prep: split fp32 -> bf16 hi/lo for nf + 6 weights ----------------
__global__ void prep_kernel(const float* __restrict__ nf,
                            const float* __restrict__ Wq, const float* __restrict__ Wk,
                            const float* __restrict__ Wv, const float* __restrict__ Wo,
                            const float* __restrict__ W1, const float* __restrict__ W2) {
    int t = blockIdx.x * 256 + threadIdx.x;
    const float* s; __nv_bfloat16 *dh, *dl; int off;
    if      (t <  524288) { s = nf; dh = g_nfH; dl = g_nfL; off = t; }
    else if (t <  589824) { s = Wq; dh = g_WqH; dl = g_WqL; off = t - 524288; }
    else if (t <  655360) { s = Wk; dh = g_WkH; dl = g_WkL; off = t - 589824; }
    else if (t <  720896) { s = Wv; dh = g_WvH; dl = g_WvL; off = t - 655360; }
    else if (t <  786432) { s = Wo; dh = g_WoH; dl = g_WoL; off = t - 720896; }
    else if (t < 1048576) { s = W1; dh = g_W1H; dl = g_W1L; off = t - 786432; }
    else if (t < 1310720) { s = W2; dh = g_W2H; dl = g_W2L; off = t - 1048576; }
    else return;
    float v = s[off];
    __nv_bfloat16 h = __float2bfloat16(v);
    dh[off] = h;
    dl[off] = __float2bfloat16(v - __bfloat162float(h));
}

// ---------------- init ----------------
__global__ void clear_kernel() {
    int tid = blockIdx.x * blockDim.x + threadIdx.x;
    if (tid < NN * NN) g_bidx[tid] = -1;
    if (tid < NN * NN / 32) g_adj[tid] = 0u;
    if (tid < NN * DD) { g_proj[tid] = 0.f; g_f2[tid] = 0.f; }
}

// ---------------- edge bias ----------------
__global__ void edge_bias_kernel(const float* __restrict__ ef,
                                 const float* __restrict__ We,
                                 const float* __restrict__ be) {
    int tid = blockIdx.x * blockDim.x + threadIdx.x;
    if (tid >= EE * HH) return;
    int e = tid >> 3, h = tid & 7;
    float s = be[h];
    const float* row = ef + e * 10;
#pragma unroll
    for (int k = 0; k < 10; k++) s += row[k] * We[k * HH + h];
    g_ebias[tid] = s;
}

// ---------------- scatter ----------------
__global__ void scatter_kernel(const int* __restrict__ src, const int* __restrict__ dst) {
    int tid = blockIdx.x * blockDim.x + threadIdx.x;
    if (tid < EE) {
        int s = src[tid], d = dst[tid];
        int p1 = s * NN + d;
        int p2 = d * NN + s;
        atomicOr(&g_adj[p1 >> 5], 1u << (p1 & 31));
        atomicOr(&g_adj[p2 >> 5], 1u << (p2 & 31));
        atomicMax(&g_bidx[p1], tid);
    } else if (tid < EE + NN) {
        int i = tid - EE;
        int p = i * NN + i;
        atomicOr(&g_adj[p >> 5], 1u << (p & 31));
    }
}

// ---------------- sparse attention: 1 block/node, 1 warp/head; writes hi/lo ------
__global__ void attn_kernel() {
    int i = blockIdx.x;
    int lane = threadIdx.x & 31;
    int h = threadIdx.x >> 5;
    __shared__ unsigned adjw[64];
    if (threadIdx.x < 64) adjw[threadIdx.x] = g_adj[i * 64 + threadIdx.x];
    __syncthreads();

    float q = g_Q[i * DD + h * HDm + lane];
    float m = -1e30f, l = 0.f, acc = 0.f;
    const float scale = 0.17677669529663687f;

    for (int wi = 0; wi < 64; wi++) {
        unsigned w = adjw[wi];
        while (w) {
            int b = __ffs(w) - 1;
            w &= w - 1;
            int j = wi * 32 + b;
            float s = q * g_K[j * DD + h * HDm + lane];
#pragma unroll
            for (int o = 16; o > 0; o >>= 1) s += __shfl_xor_sync(0xffffffffu, s, o);
            s *= scale;
            int idx = g_bidx[i * NN + j];
            if (idx >= 0) s += g_ebias[idx * HH + h];
            float nm = fmaxf(m, s);
            float es = __expf(s - nm);
            float sc = __expf(m - nm);
            l = l * sc + es;
            acc = acc * sc + es * g_V[j * DD + h * HDm + lane];
            m = nm;
        }
    }
    float v = acc / l;
    __nv_bfloat16 hi = __float2bfloat16(v);
    int idx = i * DD + h * HDm + lane;
    g_attH[idx] = hi;
    g_attL[idx] = __float2bfloat16(v - __bfloat162float(hi));
}

// ---------------- fused add(+extra bias) + LayerNorm, optional bf16 pair out ------
__global__ void add_ln_kernel(const float* __restrict__ x, const float* __restrict__ res,
                              const float* __restrict__ eb,
                              const float* __restrict__ w, const float* __restrict__ b,
                              float* __restrict__ out,
                              __nv_bfloat16* __restrict__ outH, __nv_bfloat16* __restrict__ outL,
                              int writePair) {
    int i = blockIdx.x, t = threadIdx.x;
    float v = x[i * DD + t] + res[i * DD + t] + eb[t];
    float a = v, a2 = v * v;
#pragma unroll
    for (int o = 16; o > 0; o >>= 1) {
        a += __shfl_xor_sync(0xffffffffu, a, o);
        a2 += __shfl_xor_sync(0xffffffffu, a2, o);
    }
    __shared__ float s1[8], s2[8];
    int warp = t >> 5, lane = t & 31;
    if (lane == 0) { s1[warp] = a; s2[warp] = a2; }
    __syncthreads();
    if (t < 32) {
        float x1 = (t < 8) ? s1[t] : 0.f;
        float x2 = (t < 8) ? s2[t] : 0.f;
#pragma unroll
        for (int o = 4; o > 0; o >>= 1) {
            x1 += __shfl_xor_sync(0xffffffffu, x1, o);
            x2 += __shfl_xor_sync(0xffffffffu, x2, o);
        }
        if (t == 0) { s1[0] = x1; s2[0] = x2; }
    }
    __syncthreads();
    float mu = s1[0] * (1.f / 256.f);
    float var = s2[0] * (1.f / 256.f) - mu * mu;
    float r = (v - mu) * rsqrtf(var + 1e-5f) * w[t] + b[t];
    out[i * DD + t] = r;
    if (writePair) {
        __nv_bfloat16 hi = __float2bfloat16(r);
        outH[i * DD + t] = hi;
        outL[i * DD + t] = __float2bfloat16(r - __bfloat162float(hi));
    }
}

// ---------------- launch ----------------
extern "C" void kernel_launch(void* const* d_in, const int* in_sizes, int n_in,
                              void* d_out, int out_size) {
    const float* node_feat = (const float*)d_in[0];
    const float* edge_feat = (const float*)d_in[1];
    const int*   src       = (const int*)d_in[2];
    const int*   dst       = (const int*)d_in[3];
    const float* Wq = (const float*)d_in[4];  const float* bq = (const float*)d_in[5];
    const float* Wk = (const float*)d_in[6];  const float* bk = (const float*)d_in[7];
    const float* Wv = (const float*)d_in[8];  const float* bv = (const float*)d_in[9];
    const float* Wo = (const float*)d_in[10]; const float* bo = (const float*)d_in[11];
    const float* We = (const float*)d_in[12]; const float* be = (const float*)d_in[13];
    const float* n1w = (const float*)d_in[14]; const float* n1b = (const float*)d_in[15];
    const float* W1 = (const float*)d_in[16]; const float* b1 = (const float*)d_in[17];
    const float* W2 = (const float*)d_in[18]; const float* b2 = (const float*)d_in[19];
    const float* n2w = (const float*)d_in[20]; const float* n2b = (const float*)d_in[21];
    float* out = (float*)d_out;

    float *Qp, *Kp, *Vp, *projp, *h1p, *f2p;
    cudaGetSymbolAddress((void**)&Qp, g_Q);
    cudaGetSymbolAddress((void**)&Kp, g_K);
    cudaGetSymbolAddress((void**)&Vp, g_V);
    cudaGetSymbolAddress((void**)&projp, g_proj);
    cudaGetSymbolAddress((void**)&h1p, g_h1);
    cudaGetSymbolAddress((void**)&f2p, g_f2);
    __nv_bfloat16 *nfH, *nfL, *WqH, *WqL, *WkH, *WkL, *WvH, *WvL, *WoH, *WoL,
                  *W1H, *W1L, *W2H, *W2L, *attH, *attL, *h1H, *h1L, *f1H, *f1L;
    cudaGetSymbolAddress((void**)&nfH, g_nfH);   cudaGetSymbolAddress((void**)&nfL, g_nfL);
    cudaGetSymbolAddress((void**)&WqH, g_WqH);   cudaGetSymbolAddress((void**)&WqL, g_WqL);
    cudaGetSymbolAddress((void**)&WkH, g_WkH);   cudaGetSymbolAddress((void**)&WkL, g_WkL);
    cudaGetSymbolAddress((void**)&WvH, g_WvH);   cudaGetSymbolAddress((void**)&WvL, g_WvL);
    cudaGetSymbolAddress((void**)&WoH, g_WoH);   cudaGetSymbolAddress((void**)&WoL, g_WoL);
    cudaGetSymbolAddress((void**)&W1H, g_W1H);   cudaGetSymbolAddress((void**)&W1L, g_W1L);
    cudaGetSymbolAddress((void**)&W2H, g_W2H);   cudaGetSymbolAddress((void**)&W2L, g_W2L);
    cudaGetSymbolAddress((void**)&attH, g_attH); cudaGetSymbolAddress((void**)&attL, g_attL);
    cudaGetSymbolAddress((void**)&h1H, g_h1H);   cudaGetSymbolAddress((void**)&h1L, g_h1L);
    cudaGetSymbolAddress((void**)&f1H, g_f1H);   cudaGetSymbolAddress((void**)&f1L, g_f1L);

    clear_kernel<<<(NN * NN + 255) / 256, 256>>>();
    prep_kernel<<<5120, 256>>>(node_feat, Wq, Wk, Wv, Wo, W1, W2);
    edge_bias_kernel<<<(EE * HH + 255) / 256, 256>>>(edge_feat, We, be);
    scatter_kernel<<<(EE + NN + 255) / 256, 256>>>(src, dst);

    // QKV fused (z = weight select), bias, f32 out. grid (4,32,3)=384
    gemm_tc<<<dim3(DD / 64, NN / 64, 3), 128>>>(
        nfH, nfL, WqH, WkH, WvH, WqL, WkL, WvL, bq, bk, bv,
        Qp, Kp, Vp, nullptr, nullptr, DD, DD, 8);

    attn_kernel<<<NN, 256>>>();

    // Wo: split-K=2, atomicAdd into zeroed proj (bias folded into LN). grid (4,32,2)=256
    gemm_tc<<<dim3(DD / 64, NN / 64, 2), 128>>>(
        attH, attL, WoH, WoH, WoH, WoL, WoL, WoL, bo, bo, bo,
        projp, projp, projp, nullptr, nullptr, DD, DD, 2);

    add_ln_kernel<<<NN, 256>>>(projp, node_feat, bo, n1w, n1b, h1p, h1H, h1L, 1);

    // FFN1: bias+relu, bf16 pair out. grid (16,32)=512
    gemm_tc<<<dim3(DFF / 64, NN / 64, 1), 128>>>(
        h1H, h1L, W1H, W1H, W1H, W1L, W1L, W1L, b1, b1, b1,
        nullptr, nullptr, nullptr, f1H, f1L, DD, DFF, 1 | 4);

    // FFN2: split-K=4, atomicAdd into zeroed f2 (b2 folded into LN). grid (4,32,4)=512
    gemm_tc<<<dim3(DD / 64, NN / 64, 4), 128>>>(
        f1H, f1L, W2H, W2H, W2H, W2L, W2L, W2L, b2, b2, b2,
        f2p, f2p, f2p, nullptr, nullptr, DFF, DD, 2);

    add_ln_kernel<<<NN, 256>>>(h1p, f2p, b2, n2w, n2b, out, nullptr, nullptr, 0);
}

// round 5
// speedup vs baseline: 1.9159x; 1.0414x over previous
#include <cuda_runtime.h>
#include <cuda_bf16.h>
#include <math.h>
#include <stdint.h>

#define NN 2048
#define EE 32768
#define DD 256
#define HH 8
#define HDm 32
#define DFF 1024

// ---------------- scratch (device globals; zero-initialized at load) ----------------
__device__ float    g_Q[NN * DD];
__device__ float    g_K[NN * DD];
__device__ float    g_V[NN * DD];
__device__ float    g_proj[2 * NN * DD];     // Wo split-K slices
__device__ float    g_h1[NN * DD];
__device__ float    g_f2[4 * NN * DD];       // FFN2 split-K slices
__device__ float    g_ebias[EE * HH];
__device__ unsigned g_adj[NN * NN / 32];     // adjacency bitmap  (idempotent OR)
__device__ unsigned g_hasb[NN * NN / 32];    // forward-edge bias bitmap (idempotent OR)
__device__ int      g_bidx[NN * NN];         // winning edge idx (idempotent MAX, 0-init ok)

// bf16 hi/lo pairs (pre-split fp32)
__device__ __nv_bfloat16 g_nfH[NN * DD],  g_nfL[NN * DD];
__device__ __nv_bfloat16 g_WqH[DD * DD],  g_WqL[DD * DD];
__device__ __nv_bfloat16 g_WkH[DD * DD],  g_WkL[DD * DD];
__device__ __nv_bfloat16 g_WvH[DD * DD],  g_WvL[DD * DD];
__device__ __nv_bfloat16 g_WoH[DD * DD],  g_WoL[DD * DD];
__device__ __nv_bfloat16 g_W1H[DD * DFF], g_W1L[DD * DFF];
__device__ __nv_bfloat16 g_W2H[DFF * DD], g_W2L[DFF * DD];
__device__ __nv_bfloat16 g_attH[NN * DD], g_attL[NN * DD];
__device__ __nv_bfloat16 g_h1H[NN * DD],  g_h1L[NN * DD];
__device__ __nv_bfloat16 g_f1H[NN * DFF], g_f1L[NN * DFF];

// ---------------- helpers ----------------
__device__ __forceinline__ uint32_t smem_u32(const void* p) {
    uint32_t a;
    asm("{ .reg .u64 t; cvta.to.shared.u64 t, %1; cvt.u32.u64 %0, t; }" : "=r"(a) : "l"(p));
    return a;
}
__device__ __forceinline__ void mma_bf16(float* d, const uint32_t* a, const uint32_t* b) {
    asm volatile(
        "mma.sync.aligned.m16n8k16.row.col.f32.bf16.bf16.f32 "
        "{%0,%1,%2,%3}, {%4,%5,%6,%7}, {%8,%9}, {%0,%1,%2,%3};"
        : "+f"(d[0]), "+f"(d[1]), "+f"(d[2]), "+f"(d[3])
        : "r"(a[0]), "r"(a[1]), "r"(a[2]), "r"(a[3]), "r"(b[0]), "r"(b[1]));
}
#define LDSM4(d0, d1, d2, d3, a) \
    asm volatile("ldmatrix.sync.aligned.m8n8.x4.shared.b16 {%0,%1,%2,%3},[%4];" \
        : "=r"(d0), "=r"(d1), "=r"(d2), "=r"(d3) : "r"(a))
#define LDSM4T(d0, d1, d2, d3, a) \
    asm volatile("ldmatrix.sync.aligned.m8n8.x4.trans.shared.b16 {%0,%1,%2,%3},[%4];" \
        : "=r"(d0), "=r"(d1), "=r"(d2), "=r"(d3) : "r"(a))

__device__ __forceinline__ uint32_t pack_hi(float f0, float f1) {
    __nv_bfloat16 h0 = __float2bfloat16(f0), h1 = __float2bfloat16(f1);
    return (uint32_t)__bfloat16_as_ushort(h0) | ((uint32_t)__bfloat16_as_ushort(h1) << 16);
}
__device__ __forceinline__ uint32_t pack_lo(float f0, float f1) {
    __nv_bfloat16 h0 = __float2bfloat16(f0), h1 = __float2bfloat16(f1);
    __nv_bfloat16 l0 = __float2bfloat16(f0 - __bfloat162float(h0));
    __nv_bfloat16 l1 = __float2bfloat16(f1 - __bfloat162float(h1));
    return (uint32_t)__bfloat16_as_ushort(l0) | ((uint32_t)__bfloat16_as_ushort(l1) << 16);
}

// ================= GEMM: 64x64 tile, BK=32, 4 warps, ldmatrix, bf16 hi/lo =================
// flags: 1=RELU, 2=SPLITK (slice -> C + z*NN*N, no bias), 4=OUT_PAIR, 8=z selects weight set
#define ASTR 40
#define BSTR 72

__global__ void __launch_bounds__(128) gemm_tc(
    const __nv_bfloat16* __restrict__ AH, const __nv_bfloat16* __restrict__ AL,
    const __nv_bfloat16* __restrict__ BH0, const __nv_bfloat16* __restrict__ BH1, const __nv_bfloat16* __restrict__ BH2,
    const __nv_bfloat16* __restrict__ BL0, const __nv_bfloat16* __restrict__ BL1, const __nv_bfloat16* __restrict__ BL2,
    const float* __restrict__ bias0, const float* __restrict__ bias1, const float* __restrict__ bias2,
    float* __restrict__ C0, float* __restrict__ C1, float* __restrict__ C2,
    __nv_bfloat16* __restrict__ CH, __nv_bfloat16* __restrict__ CL,
    int K, int N, int flags)
{
    __shared__ __align__(16) __nv_bfloat16 AsH[64 * ASTR];
    __shared__ __align__(16) __nv_bfloat16 AsL[64 * ASTR];
    __shared__ __align__(16) __nv_bfloat16 BsH[32 * BSTR];
    __shared__ __align__(16) __nv_bfloat16 BsL[32 * BSTR];

    const __nv_bfloat16* BH = BH0; const __nv_bfloat16* BL = BL0;
    const float* bias = bias0; float* C = C0;
    int kslice = 0, nsl = 1;
    if (flags & 8) {
        if (blockIdx.z == 1) { BH = BH1; BL = BL1; bias = bias1; C = C1; }
        else if (blockIdx.z == 2) { BH = BH2; BL = BL2; bias = bias2; C = C2; }
    } else if (flags & 2) {
        kslice = blockIdx.z; nsl = gridDim.z;
        C = C0 + (size_t)kslice * NN * N;
    }

    const int tid = threadIdx.x;
    const int lane = tid & 31;
    const int wid = tid >> 5;
    const int wm = wid >> 1, wn = wid & 1;
    const int g = lane >> 2, tg = lane & 3;
    const int m0 = blockIdx.y * 64;
    const int n0 = blockIdx.x * 64;

    const int nk = (K >> 5) / nsl;
    const int kstart = kslice * nk;

    float acc[2][4][4];
#pragma unroll
    for (int i = 0; i < 2; i++)
#pragma unroll
        for (int j = 0; j < 4; j++)
#pragma unroll
            for (int c = 0; c < 4; c++) acc[i][j][c] = 0.f;

    const uint32_t aBaseH = smem_u32(AsH) + (((wm * 32 + (lane & 15)) * ASTR + ((lane >> 4) << 3)) << 1);
    const uint32_t aBaseL = smem_u32(AsL) + (((wm * 32 + (lane & 15)) * ASTR + ((lane >> 4) << 3)) << 1);
    const uint32_t bBaseH = smem_u32(BsH) + ((((lane & 15)) * BSTR + wn * 32 + ((lane >> 4) << 3)) << 1);
    const uint32_t bBaseL = smem_u32(BsL) + ((((lane & 15)) * BSTR + wn * 32 + ((lane >> 4) << 3)) << 1);

    uint2 rAH[4], rAL[4], rBH[4], rBL[4];

#define LOADC(KC) do { \
    _Pragma("unroll") \
    for (int it = 0; it < 4; it++) { \
        int flat = tid * 4 + it * 512; \
        int r = flat >> 5, c = flat & 31; \
        size_t gi = (size_t)(m0 + r) * K + (KC) * 32 + c; \
        rAH[it] = *(const uint2*)(AH + gi); \
        rAL[it] = *(const uint2*)(AL + gi); \
        int k = flat >> 6, n = flat & 63; \
        size_t gj = (size_t)((KC) * 32 + k) * N + n0 + n; \
        rBH[it] = *(const uint2*)(BH + gj); \
        rBL[it] = *(const uint2*)(BL + gj); \
    } } while (0)

    LOADC(kstart);

    for (int kc = 0; kc < nk; kc++) {
#pragma unroll
        for (int it = 0; it < 4; it++) {
            int flat = tid * 4 + it * 512;
            int r = flat >> 5, c = flat & 31;
            *(uint2*)&AsH[r * ASTR + c] = rAH[it];
            *(uint2*)&AsL[r * ASTR + c] = rAL[it];
            int k = flat >> 6, n = flat & 63;
            *(uint2*)&BsH[k * BSTR + n] = rBH[it];
            *(uint2*)&BsL[k * BSTR + n] = rBL[it];
        }
        __syncthreads();
        if (kc + 1 < nk) LOADC(kstart + kc + 1);

#pragma unroll
        for (int kk = 0; kk < 2; kk++) {
            const int kb = kk * 16;
            uint32_t ah[2][4], al[2][4], bh[4][2], bl[4][2];
            LDSM4(ah[0][0], ah[0][1], ah[0][2], ah[0][3], aBaseH + (kb << 1));
            LDSM4(ah[1][0], ah[1][1], ah[1][2], ah[1][3], aBaseH + ((16 * ASTR + kb) << 1));
            LDSM4(al[0][0], al[0][1], al[0][2], al[0][3], aBaseL + (kb << 1));
            LDSM4(al[1][0], al[1][1], al[1][2], al[1][3], aBaseL + ((16 * ASTR + kb) << 1));
            LDSM4T(bh[0][0], bh[0][1], bh[1][0], bh[1][1], bBaseH + ((kb * BSTR) << 1));
            LDSM4T(bh[2][0], bh[2][1], bh[3][0], bh[3][1], bBaseH + ((kb * BSTR + 16) << 1));
            LDSM4T(bl[0][0], bl[0][1], bl[1][0], bl[1][1], bBaseL + ((kb * BSTR) << 1));
            LDSM4T(bl[2][0], bl[2][1], bl[3][0], bl[3][1], bBaseL + ((kb * BSTR + 16) << 1));
#pragma unroll
            for (int i = 0; i < 2; i++)
#pragma unroll
                for (int j = 0; j < 4; j++) mma_bf16(acc[i][j], ah[i], bh[j]);
#pragma unroll
            for (int i = 0; i < 2; i++)
#pragma unroll
                for (int j = 0; j < 4; j++) mma_bf16(acc[i][j], ah[i], bl[j]);
#pragma unroll
            for (int i = 0; i < 2; i++)
#pragma unroll
                for (int j = 0; j < 4; j++) mma_bf16(acc[i][j], al[i], bh[j]);
        }
        __syncthreads();
    }

    // ---- epilogue ----
#pragma unroll
    for (int i = 0; i < 2; i++) {
        int row = m0 + wm * 32 + i * 16 + g;
#pragma unroll
        for (int j = 0; j < 4; j++) {
            int col = n0 + wn * 32 + j * 8 + tg * 2;
            float v0 = acc[i][j][0], v1 = acc[i][j][1], v2 = acc[i][j][2], v3 = acc[i][j][3];
            if (flags & 2) {
                *(float2*)(C + (size_t)row * N + col) = make_float2(v0, v1);
                *(float2*)(C + (size_t)(row + 8) * N + col) = make_float2(v2, v3);
            } else {
                float b0f = bias[col], b1f = bias[col + 1];
                v0 += b0f; v1 += b1f; v2 += b0f; v3 += b1f;
                if (flags & 1) {
                    v0 = fmaxf(v0, 0.f); v1 = fmaxf(v1, 0.f);
                    v2 = fmaxf(v2, 0.f); v3 = fmaxf(v3, 0.f);
                }
                if (flags & 4) {
                    *(uint32_t*)&CH[(size_t)row * N + col] = pack_hi(v0, v1);
                    *(uint32_t*)&CL[(size_t)row * N + col] = pack_lo(v0, v1);
                    *(uint32_t*)&CH[(size_t)(row + 8) * N + col] = pack_hi(v2, v3);
                    *(uint32_t*)&CL[(size_t)(row + 8) * N + col] = pack_lo(v2, v3);
                } else {
                    *(float2*)(C + (size_t)row * N + col) = make_float2(v0, v1);
                    *(float2*)(C + (size_t)(row + 8) * N + col) = make_float2(v2, v3);
                }
            }
        }
    }
}

// ---------------- prep: split fp32 -> bf16 hi/lo for nf + 6 weights ----------------
__global__ void prep_kernel(const float* __restrict__ nf,
                            const float* __restrict__ Wq, const float* __restrict__ Wk,
                            const float* __restrict__ Wv, const float* __restrict__ Wo,
                            const float* __restrict__ W1, const float* __restrict__ W2) {
    int t = blockIdx.x * 256 + threadIdx.x;
    const float* s; __nv_bfloat16 *dh, *dl; int off;
    if      (t <  524288) { s = nf; dh = g_nfH; dl = g_nfL; off = t; }
    else if (t <  589824) { s = Wq; dh = g_WqH; dl = g_WqL; off = t - 524288; }
    else if (t <  655360) { s = Wk; dh = g_WkH; dl = g_WkL; off = t - 589824; }
    else if (t <  720896) { s = Wv; dh = g_WvH; dl = g_WvL; off = t - 655360; }
    else if (t <  786432) { s = Wo; dh = g_WoH; dl = g_WoL; off = t - 720896; }
    else if (t < 1048576) { s = W1; dh = g_W1H; dl = g_W1L; off = t - 786432; }
    else if (t < 1310720) { s = W2; dh = g_W2H; dl = g_W2L; off = t - 1048576; }
    else return;
    float v = s[off];
    __nv_bfloat16 h = __float2bfloat16(v);
    dh[off] = h;
    dl[off] = __float2bfloat16(v - __bfloat162float(h));
}

// ------- fused edge-bias + scatter (all writes idempotent; no clearing needed) -------
__global__ void scatter_kernel(const int* __restrict__ src, const int* __restrict__ dst,
                               const float* __restrict__ ef,
                               const float* __restrict__ We, const float* __restrict__ be) {
    int tid = blockIdx.x * blockDim.x + threadIdx.x;
    if (tid < EE) {
        const float* row = ef + tid * 10;
        float r[10];
#pragma unroll
        for (int k = 0; k < 10; k++) r[k] = row[k];
#pragma unroll
        for (int h = 0; h < HH; h++) {
            float s = be[h];
#pragma unroll
            for (int k = 0; k < 10; k++) s = fmaf(r[k], We[k * HH + h], s);
            g_ebias[tid * HH + h] = s;
        }
        int s = src[tid], d = dst[tid];
        int p1 = s * NN + d;
        int p2 = d * NN + s;
        atomicOr(&g_adj[p1 >> 5], 1u << (p1 & 31));
        atomicOr(&g_adj[p2 >> 5], 1u << (p2 & 31));
        atomicOr(&g_hasb[p1 >> 5], 1u << (p1 & 31));
        atomicMax(&g_bidx[p1], tid);    // 0-init fine: indices >= 0, max = last-write
    } else if (tid < EE + NN) {
        int i = tid - EE;
        int p = i * NN + i;
        atomicOr(&g_adj[p >> 5], 1u << (p & 31));
    }
}

// ------- sparse attention: 1 block/node, 1 warp/head, batch-4 online softmax -------
__global__ void attn_kernel() {
    int i = blockIdx.x;
    int lane = threadIdx.x & 31;
    int h = threadIdx.x >> 5;
    __shared__ unsigned adjw[64];
    if (threadIdx.x < 64) adjw[threadIdx.x] = g_adj[i * 64 + threadIdx.x];
    __syncthreads();

    const float* Kb = g_K + h * HDm + lane;
    const float* Vb = g_V + h * HDm + lane;
    float q = g_Q[i * DD + h * HDm + lane];
    float m = -1e30f, l = 0.f, acc = 0.f;
    const float scale = 0.17677669529663687f;

    int wi = 0;
    unsigned w = adjw[0];
    for (;;) {
        int js[4]; int nb = 0;
        while (nb < 4) {
            while (w == 0 && wi < 63) w = adjw[++wi];
            if (w == 0) break;
            int b = __ffs(w) - 1; w &= w - 1;
            js[nb++] = wi * 32 + b;
        }
        if (nb == 0) break;

        float s[4], vv[4];
#pragma unroll
        for (int b = 0; b < 4; b++) {
            int j = js[b < nb ? b : 0];
            s[b] = q * Kb[(size_t)j * DD];
            vv[b] = Vb[(size_t)j * DD];
        }
#pragma unroll
        for (int o = 16; o > 0; o >>= 1) {
#pragma unroll
            for (int b = 0; b < 4; b++) s[b] += __shfl_xor_sync(0xffffffffu, s[b], o);
        }
#pragma unroll
        for (int b = 0; b < 4; b++) {
            if (b < nb) {
                int p = i * NN + js[b];
                float bias = 0.f;
                if ((g_hasb[p >> 5] >> (p & 31)) & 1u) bias = g_ebias[g_bidx[p] * HH + h];
                s[b] = s[b] * scale + bias;
            } else {
                s[b] = -1e30f; vv[b] = 0.f;
            }
        }
        float bm = fmaxf(fmaxf(s[0], s[1]), fmaxf(s[2], s[3]));
        float nm = fmaxf(m, bm);
        float sc = __expf(m - nm);
        float e0 = __expf(s[0] - nm), e1 = __expf(s[1] - nm);
        float e2 = __expf(s[2] - nm), e3 = __expf(s[3] - nm);
        l = l * sc + (e0 + e1) + (e2 + e3);
        acc = acc * sc + (e0 * vv[0] + e1 * vv[1]) + (e2 * vv[2] + e3 * vv[3]);
        m = nm;
    }
    float v = acc / l;
    __nv_bfloat16 hi = __float2bfloat16(v);
    int idx = i * DD + h * HDm + lane;
    g_attH[idx] = hi;
    g_attL[idx] = __float2bfloat16(v - __bfloat162float(hi));
}

// -------- fused slice-sum + residual + bias + LayerNorm, optional bf16 pair out --------
__global__ void add_ln_kernel(const float* __restrict__ x, int nslices,
                              const float* __restrict__ res, const float* __restrict__ eb,
                              const float* __restrict__ w, const float* __restrict__ b,
                              float* __restrict__ out,
                              __nv_bfloat16* __restrict__ outH, __nv_bfloat16* __restrict__ outL,
                              int writePair) {
    int i = blockIdx.x, t = threadIdx.x;
    float v = res[i * DD + t] + eb[t];
    for (int s = 0; s < nslices; s++) v += x[(size_t)s * NN * DD + i * DD + t];
    float a = v, a2 = v * v;
#pragma unroll
    for (int o = 16; o > 0; o >>= 1) {
        a += __shfl_xor_sync(0xffffffffu, a, o);
        a2 += __shfl_xor_sync(0xffffffffu, a2, o);
    }
    __shared__ float s1[8], s2[8];
    int warp = t >> 5, lane = t & 31;
    if (lane == 0) { s1[warp] = a; s2[warp] = a2; }
    __syncthreads();
    if (t < 32) {
        float x1 = (t < 8) ? s1[t] : 0.f;
        float x2 = (t < 8) ? s2[t] : 0.f;
#pragma unroll
        for (int o = 4; o > 0; o >>= 1) {
            x1 += __shfl_xor_sync(0xffffffffu, x1, o);
            x2 += __shfl_xor_sync(0xffffffffu, x2, o);
        }
        if (t == 0) { s1[0] = x1; s2[0] = x2; }
    }
    __syncthreads();
    float mu = s1[0] * (1.f / 256.f);
    float var = s2[0] * (1.f / 256.f) - mu * mu;
    float r = (v - mu) * rsqrtf(var + 1e-5f) * w[t] + b[t];
    out[i * DD + t] = r;
    if (writePair) {
        __nv_bfloat16 hi = __float2bfloat16(r);
        outH[i * DD + t] = hi;
        outL[i * DD + t] = __float2bfloat16(r - __bfloat162float(hi));
    }
}

// ---------------- launch ----------------
extern "C" void kernel_launch(void* const* d_in, const int* in_sizes, int n_in,
                              void* d_out, int out_size) {
    const float* node_feat = (const float*)d_in[0];
    const float* edge_feat = (const float*)d_in[1];
    const int*   src       = (const int*)d_in[2];
    const int*   dst       = (const int*)d_in[3];
    const float* Wq = (const float*)d_in[4];  const float* bq = (const float*)d_in[5];
    const float* Wk = (const float*)d_in[6];  const float* bk = (const float*)d_in[7];
    const float* Wv = (const float*)d_in[8];  const float* bv = (const float*)d_in[9];
    const float* Wo = (const float*)d_in[10]; const float* bo = (const float*)d_in[11];
    const float* We = (const float*)d_in[12]; const float* be = (const float*)d_in[13];
    const float* n1w = (const float*)d_in[14]; const float* n1b = (const float*)d_in[15];
    const float* W1 = (const float*)d_in[16]; const float* b1 = (const float*)d_in[17];
    const float* W2 = (const float*)d_in[18]; const float* b2 = (const float*)d_in[19];
    const float* n2w = (const float*)d_in[20]; const float* n2b = (const float*)d_in[21];
    float* out = (float*)d_out;

    float *Qp, *Kp, *Vp, *projp, *h1p, *f2p;
    cudaGetSymbolAddress((void**)&Qp, g_Q);
    cudaGetSymbolAddress((void**)&Kp, g_K);
    cudaGetSymbolAddress((void**)&Vp, g_V);
    cudaGetSymbolAddress((void**)&projp, g_proj);
    cudaGetSymbolAddress((void**)&h1p, g_h1);
    cudaGetSymbolAddress((void**)&f2p, g_f2);
    __nv_bfloat16 *nfH, *nfL, *WqH, *WqL, *WkH, *WkL, *WvH, *WvL, *WoH, *WoL,
                  *W1H, *W1L, *W2H, *W2L, *attH, *attL, *h1H, *h1L, *f1H, *f1L;
    cudaGetSymbolAddress((void**)&nfH, g_nfH);   cudaGetSymbolAddress((void**)&nfL, g_nfL);
    cudaGetSymbolAddress((void**)&WqH, g_WqH);   cudaGetSymbolAddress((void**)&WqL, g_WqL);
    cudaGetSymbolAddress((void**)&WkH, g_WkH);   cudaGetSymbolAddress((void**)&WkL, g_WkL);
    cudaGetSymbolAddress((void**)&WvH, g_WvH);   cudaGetSymbolAddress((void**)&WvL, g_WvL);
    cudaGetSymbolAddress((void**)&WoH, g_WoH);   cudaGetSymbolAddress((void**)&WoL, g_WoL);
    cudaGetSymbolAddress((void**)&W1H, g_W1H);   cudaGetSymbolAddress((void**)&W1L, g_W1L);
    cudaGetSymbolAddress((void**)&W2H, g_W2H);   cudaGetSymbolAddress((void**)&W2L, g_W2L);
    cudaGetSymbolAddress((void**)&attH, g_attH); cudaGetSymbolAddress((void**)&attL, g_attL);
    cudaGetSymbolAddress((void**)&h1H, g_h1H);   cudaGetSymbolAddress((void**)&h1L, g_h1L);
    cudaGetSymbolAddress((void**)&f1H, g_f1H);   cudaGetSymbolAddress((void**)&f1L, g_f1L);

    prep_kernel<<<5120, 256>>>(node_feat, Wq, Wk, Wv, Wo, W1, W2);
    scatter_kernel<<<(EE + NN + 255) / 256, 256>>>(src, dst, edge_feat, We, be);

    // QKV fused (z = weight select). grid (4,32,3)=384
    gemm_tc<<<dim3(DD / 64, NN / 64, 3), 128>>>(
        nfH, nfL, WqH, WkH, WvH, WqL, WkL, WvL, bq, bk, bv,
        Qp, Kp, Vp, nullptr, nullptr, DD, DD, 8);

    attn_kernel<<<NN, 256>>>();

    // Wo: split-K=2 into slice buffers (bias folded into LN). grid (4,32,2)=256
    gemm_tc<<<dim3(DD / 64, NN / 64, 2), 128>>>(
        attH, attL, WoH, WoH, WoH, WoL, WoL, WoL, bo, bo, bo,
        projp, nullptr, nullptr, nullptr, nullptr, DD, DD, 2);

    add_ln_kernel<<<NN, 256>>>(projp, 2, node_feat, bo, n1w, n1b, h1p, h1H, h1L, 1);

    // FFN1: bias+relu, bf16 pair out. grid (16,32)=512
    gemm_tc<<<dim3(DFF / 64, NN / 64, 1), 128>>>(
        h1H, h1L, W1H, W1H, W1H, W1L, W1L, W1L, b1, b1, b1,
        nullptr, nullptr, nullptr, f1H, f1L, DD, DFF, 1 | 4);

    // FFN2: split-K=4 into slice buffers (b2 folded into LN). grid (4,32,4)=512
    gemm_tc<<<dim3(DD / 64, NN / 64, 4), 128>>>(
        f1H, f1L, W2H, W2H, W2H, W2L, W2L, W2L, b2, b2, b2,
        f2p, nullptr, nullptr, nullptr, nullptr, DFF, DD, 2);

    add_ln_kernel<<<NN, 256>>>(f2p, 4, h1p, b2, n2w, n2b, out, nullptr, nullptr, 0);
}